// round 14
// baseline (speedup 1.0000x reference)
#include <cuda_runtime.h>
#include <cstdint>

// Problem dims
#define NB 32
#define C  64
#define H  128
#define W  128
#define CO 64
#define HO 64
#define WO 64

#define NSM    148
#define NBLK   (NSM * 6)          // persistent grid, <= residency
#define NPACK  1024               // 32 batches x 32 4-row groups
#define NCONV  1024               // 32 batches x 32 2-row output groups
#define NITEMS (NPACK + NCONV)

// Scratch + queue state
__device__ uint64_t g_xpack[NB * H * W];   // packed x sign bits (4 MiB, L2-resident)
__device__ uint64_t g_wpack[CO * 9];
__device__ int g_head;
__device__ int g_done[NB];                 // pack-items completed per batch

// ---------------------------------------------------------------------------
// Kernel 1: pack w sign bits + reset queue state (runs before workers).
// ---------------------------------------------------------------------------
__global__ __launch_bounds__(64) void pack_w_kernel(const float* __restrict__ w) {
    if (blockIdx.x == 0) {
        if (threadIdx.x == 0) g_head = 0;
        if (threadIdx.x < NB) g_done[threadIdx.x] = 0;
    }
    int t = blockIdx.x * 36 + threadIdx.x;
    if (threadIdx.x < 36 && t < CO * 9) {
        int co = t / 9;
        int k  = t - co * 9;
        uint32_t lo = 0, hi = 0;
        #pragma unroll 8
        for (int ci = 0; ci < 32; ++ci)
            lo |= (uint32_t)(w[(size_t)(co * 64 + ci) * 9 + k] >= 0.0f) << ci;
        #pragma unroll 8
        for (int ci = 0; ci < 32; ++ci)
            hi |= (uint32_t)(w[(size_t)(co * 64 + ci + 32) * 9 + k] >= 0.0f) << ci;
        g_wpack[t] = (uint64_t)lo | ((uint64_t)hi << 32);
    }
}

// ---------------------------------------------------------------------------
// Kernel 2: persistent workers with dynamic queue — pack and conv items
// co-resident so DRAM streaming (pack) overlaps popcount compute (conv).
// Queue order: P(b0)x32; then per batch g: alternating P(g+1,i) / C(g,i);
// tail C(b31)x32. Every C's P-dependencies precede it -> no deadlock.
//  - Pack item (b,hg): pack x rows [4hg,4hg+4) of batch b into g_xpack.
//    Release: stores -> threadfence -> syncthreads -> t0 atomicAdd(done[b]).
//  - Conv item (b,hog): spin on done[b]==32, stage 5x129 patch from g_xpack
//    (L2 hits via __ldcg), compute 2 output rows x 64 wo x 64 co exactly as
//    the proven R10 loop (1 px x 32 co per thread).
// ---------------------------------------------------------------------------
__global__ __launch_bounds__(256, 6) void qconv_worker_kernel(
        const float* __restrict__ x, float* __restrict__ out) {
    const int PW = 132;
    __shared__ uint64_t sw[CO * 9];        // 4608 B
    __shared__ uint64_t sp[5 * PW];        // 5280 B
    __shared__ int s_item;

    int tid = threadIdx.x;

    // Stage weights once per persistent block (pack_w_kernel already done).
    for (int i = tid; i < CO * 9; i += 256)
        sw[i] = g_wpack[i];

    for (;;) {
        if (tid == 0) s_item = atomicAdd(&g_head, 1);
        __syncthreads();
        int it = s_item;
        if (it >= NITEMS) break;

        // ---- decode queue position -> item ----
        bool isPack;
        int b, tile;
        if (it < 32)            { isPack = true;  b = 0;  tile = it; }
        else if (it < 32 + 31 * 64) {
            int j = it - 32, g = j >> 6, r = j & 63;
            if (r & 1)          { isPack = false; b = g;      tile = r >> 1; }
            else                { isPack = true;  b = g + 1;  tile = r >> 1; }
        }
        else                    { isPack = false; b = 31; tile = it - (32 + 31 * 64); }

        if (isPack) {
            // ---- PACK item: rows [4*tile, 4*tile+4) of batch b ----
            const float* xb = x + (size_t)b * C * (H * W);
            #pragma unroll
            for (int k = 0; k < 2; ++k) {
                int wi  = tid + k * 256;          // 0..511
                int row = wi >> 7;
                int col = wi & 127;
                int iy  = 4 * tile + row;
                const float* p = xb + iy * W + col;
                uint32_t lo = 0, hi = 0;
                #pragma unroll 16
                for (int c = 0; c < 32; ++c) {
                    lo |= (uint32_t)(__ldcs(p + (size_t)c * (H * W)) >= 0.0f) << c;
                    hi |= (uint32_t)(__ldcs(p + (size_t)(c + 32) * (H * W)) >= 0.0f) << c;
                }
                __stcg((unsigned long long*)&g_xpack[((size_t)b * H + iy) * W + col],
                       (unsigned long long)((uint64_t)lo | ((uint64_t)hi << 32)));
            }
            __threadfence();
            __syncthreads();                       // also protects s_item
            if (tid == 0) atomicAdd(&g_done[b], 1);
        } else {
            // ---- CONV item: output rows [2*tile, 2*tile+2) of batch b ----
            if (tid == 0) {
                while (((volatile int*)g_done)[b] < 32) __nanosleep(64);
            }
            __syncthreads();
            __threadfence();

            int iy0 = 4 * tile - 1;
            for (int i = tid; i < 5 * 129; i += 256) {
                int r  = i / 129;
                int cx = i - r * 129;
                int iy = iy0 + r;
                int ix = cx - 1;
                uint64_t v = 0;
                if (iy >= 0 && ix >= 0)
                    v = (uint64_t)__ldcg((const unsigned long long*)
                            &g_xpack[((size_t)b * H + iy) * W + ix]);
                sp[r * PW + cx] = v;
            }
            __syncthreads();

            int tx  = tid & 63;                // wo
            int ty  = tid >> 6;                // 0..3
            int q   = ty & 1;                  // row within tile
            int coh = (ty >> 1) * 32;          // co half
            int ho  = 2 * tile + q;

            uint32_t slo[9], shi[9];
            #pragma unroll
            for (int ky = 0; ky < 3; ++ky) {
                #pragma unroll
                for (int kx = 0; kx < 3; ++kx) {
                    int t = ky * 3 + kx;
                    uint64_t s = sp[(2 * q + ky) * PW + 2 * tx + kx];
                    slo[t] = (uint32_t)s;
                    shi[t] = (uint32_t)(s >> 32);
                }
            }
            uint32_t mr = (ho > 0) ? 0xFFFFFFFFu : 0u;
            uint32_t mc = (tx > 0) ? 0xFFFFFFFFu : 0u;
            uint32_t mb = mr & mc;
            int base = 64 * (ho > 0 ? 3 : 2) * (tx > 0 ? 3 : 2);

            float* op = out + (((size_t)b * CO + coh) * HO + ho) * WO + tx;
            const uint64_t* wbase = sw + coh * 9;

            #pragma unroll 4
            for (int co = 0; co < 32; ++co) {
                const uint64_t* wrow = wbase + co * 9;
                int acc = 0;
                #pragma unroll
                for (int t = 0; t < 9; ++t) {
                    uint64_t wv = wrow[t];     // warp-uniform broadcast LDS
                    uint32_t wl = (uint32_t)wv;
                    uint32_t wh = (uint32_t)(wv >> 32);
                    if (t == 0) {
                        acc += __popc((slo[t] ^ wl) & mb);
                        acc += __popc((shi[t] ^ wh) & mb);
                    } else if (t == 1 || t == 2) {
                        acc += __popc((slo[t] ^ wl) & mr);
                        acc += __popc((shi[t] ^ wh) & mr);
                    } else if (t == 3 || t == 6) {
                        acc += __popc((slo[t] ^ wl) & mc);
                        acc += __popc((shi[t] ^ wh) & mc);
                    } else {
                        acc += __popc(slo[t] ^ wl);
                        acc += __popc(shi[t] ^ wh);
                    }
                }
                op[(size_t)co * (HO * WO)] = (float)(base - 2 * acc);
            }
            __syncthreads();                   // protects sp and s_item
        }
    }
}

// ---------------------------------------------------------------------------
extern "C" void kernel_launch(void* const* d_in, const int* in_sizes, int n_in,
                              void* d_out, int out_size) {
    const float* x = (const float*)d_in[0];
    const float* w = (const float*)d_in[1];
    float* out = (float*)d_out;

    pack_w_kernel<<<16, 64>>>(w);
    qconv_worker_kernel<<<NBLK, 256>>>(x, out);
}

// round 15
// speedup vs baseline: 1.1557x; 1.1557x over previous
#include <cuda_runtime.h>
#include <cstdint>

// Problem dims
#define NB 32
#define C  64
#define H  128
#define W  128
#define CO 64
#define HO 64
#define WO 64

// Scratch: packed sign bits.
__device__ uint64_t g_xpack[NB * H * W];          // 4 MiB (L2-resident)
__device__ uint64_t g_wpack[CO * 9];

// ---------------------------------------------------------------------------
// Kernel 1: pack x AND w sign bits (R9 winner, unchanged).
// Blocks 0..1023: pack x, 2 px/thread, streaming __ldcs loads.
// Blocks 1024..1039: pack w, 36 (co,tap) words per block.
// ---------------------------------------------------------------------------
__global__ __launch_bounds__(256) void pack_kernel(const float* __restrict__ x,
                                                   const float* __restrict__ w) {
    if (blockIdx.x >= 1024) {
        int t = (blockIdx.x - 1024) * 36 + threadIdx.x;
        if (threadIdx.x < 36 && t < CO * 9) {
            int co = t / 9;
            int k  = t - co * 9;
            uint32_t lo = 0, hi = 0;
            #pragma unroll 8
            for (int ci = 0; ci < 32; ++ci)
                lo |= (uint32_t)(w[(size_t)(co * 64 + ci) * 9 + k] >= 0.0f) << ci;
            #pragma unroll 8
            for (int ci = 0; ci < 32; ++ci)
                hi |= (uint32_t)(w[(size_t)(co * 64 + ci + 32) * 9 + k] >= 0.0f) << ci;
            g_wpack[t] = (uint64_t)lo | ((uint64_t)hi << 32);
        }
        return;
    }

    int tid = blockIdx.x * blockDim.x + threadIdx.x;   // 0 .. 262143
    int w2 = tid & 63;
    int h  = (tid >> 6) & 127;
    int n  = tid >> 13;

    const float* base = x + (size_t)n * C * (H * W) + h * W + w2 * 2;

    uint32_t lo0 = 0, lo1 = 0, hi0 = 0, hi1 = 0;

    #pragma unroll 16
    for (int c = 0; c < 32; ++c) {
        float2 v = __ldcs(reinterpret_cast<const float2*>(base + (size_t)c * (H * W)));
        lo0 |= (uint32_t)(v.x >= 0.0f) << c;
        lo1 |= (uint32_t)(v.y >= 0.0f) << c;
    }
    #pragma unroll 16
    for (int c = 0; c < 32; ++c) {
        float2 v = __ldcs(reinterpret_cast<const float2*>(base + (size_t)(c + 32) * (H * W)));
        hi0 |= (uint32_t)(v.x >= 0.0f) << c;
        hi1 |= (uint32_t)(v.y >= 0.0f) << c;
    }

    uint64_t* op = g_xpack + ((size_t)n * H + h) * W + w2 * 2;
    op[0] = (uint64_t)lo0 | ((uint64_t)hi0 << 32);
    op[1] = (uint64_t)lo1 | ((uint64_t)hi1 << 32);
}

// ---------------------------------------------------------------------------
// Kernel 2: XNOR-popcount conv, OPERAND ROLES INVERTED.
// Lane l of each warp owns c_out (coh + l): its 9 weight words live in 18
// REGISTERS (loaded once). Warps iterate pixels; per pixel only 9 warp-
// uniform broadcast LDS feed all 32 lanes -> 9 LDS per 32 outputs instead
// of 9 per 1 output (32x LSU reduction — the plateau-setting bottleneck).
// Block = 1 output row x 64 wo x 64 co; warps 0-3 cover co 0-31 for wo
// quarters, warps 4-7 co 32-63. Results staged in padded smem (conflict-
// free transpose), then written coalesced.
// ---------------------------------------------------------------------------
__global__ __launch_bounds__(256) void qconv_bcast_kernel(float* __restrict__ out) {
    const int PW = 132;
    __shared__ uint64_t sp[3 * PW];        // 3168 B: 3 input rows, cols -1..127
    __shared__ float sbuf[64 * 65];        // 16640 B: [wo][co] padded

    int n   = blockIdx.y;
    int ho  = blockIdx.x;
    int iy0 = 2 * ho - 1;
    int tid = threadIdx.x;
    int wid = tid >> 5;
    int lane = tid & 31;
    int co  = ((wid >= 4) ? 32 : 0) + lane;

    // Per-lane weights -> registers (once per block; g_wpack is L2-hot)
    uint32_t wlo[9], whi[9];
    #pragma unroll
    for (int t = 0; t < 9; ++t) {
        uint64_t wv = g_wpack[co * 9 + t];
        wlo[t] = (uint32_t)wv;
        whi[t] = (uint32_t)(wv >> 32);
    }

    // Stage 3x129 packed input rows from g_xpack (L2 hits)
    for (int i = tid; i < 3 * 129; i += 256) {
        int r  = i / 129;
        int cx = i - r * 129;
        int iy = iy0 + r;
        int ix = cx - 1;
        uint64_t v = 0;
        if (iy >= 0 && ix >= 0)
            v = g_xpack[((size_t)n * H + iy) * W + ix];
        sp[r * PW + cx] = v;
    }
    __syncthreads();

    int px0 = (wid & 3) * 16;              // this warp's 16 wo positions
    uint32_t mr = (ho > 0) ? 0xFFFFFFFFu : 0u;
    int rowsv = (ho > 0) ? 3 : 2;

    #pragma unroll 2
    for (int u = 0; u < 16; ++u) {
        int tx = px0 + u;
        uint32_t mc = (tx > 0) ? 0xFFFFFFFFu : 0u;
        uint32_t mb = mr & mc;
        int base = 64 * rowsv * (tx > 0 ? 3 : 2);

        int acc = 0;
        #pragma unroll
        for (int ky = 0; ky < 3; ++ky) {
            // 3 warp-uniform broadcast loads feed all 32 lanes
            uint64_t s0 = sp[ky * PW + 2 * tx + 0];
            uint64_t s1 = sp[ky * PW + 2 * tx + 1];
            uint64_t s2 = sp[ky * PW + 2 * tx + 2];
            uint32_t m0  = (ky == 0) ? mb : mc;        // kx==0 tap
            uint32_t m12 = (ky == 0) ? mr : 0xFFFFFFFFu;
            int t = ky * 3;
            acc += __popc(((uint32_t)s0 ^ wlo[t])     & m0);
            acc += __popc(((uint32_t)(s0 >> 32) ^ whi[t]) & m0);
            acc += __popc(((uint32_t)s1 ^ wlo[t + 1]) & m12);
            acc += __popc(((uint32_t)(s1 >> 32) ^ whi[t + 1]) & m12);
            acc += __popc(((uint32_t)s2 ^ wlo[t + 2]) & m12);
            acc += __popc(((uint32_t)(s2 >> 32) ^ whi[t + 2]) & m12);
        }
        // [wo][co] padded: write lanes consecutive -> conflict-free
        sbuf[tx * 65 + co] = (float)(base - 2 * acc);
    }
    __syncthreads();

    // Coalesced store: consecutive threads -> consecutive wo within a co plane
    const size_t plane = (size_t)HO * WO;
    float* ob = out + ((size_t)n * CO) * plane + (size_t)ho * WO;
    for (int e = tid; e < 64 * 64; e += 256) {
        int c2 = e >> 6;
        int wo = e & 63;
        ob[(size_t)c2 * plane + wo] = sbuf[wo * 65 + c2];   // stride-65 read: conflict-free
    }
}

// ---------------------------------------------------------------------------
extern "C" void kernel_launch(void* const* d_in, const int* in_sizes, int n_in,
                              void* d_out, int out_size) {
    const float* x = (const float*)d_in[0];
    const float* w = (const float*)d_in[1];
    float* out = (float*)d_out;

    pack_kernel<<<1040, 256>>>(x, w);
    qconv_bcast_kernel<<<dim3(HO, NB), 256>>>(out);
}